// round 15
// baseline (speedup 1.0000x reference)
#include <cuda_runtime.h>

// R15: R11 champion (1435.7us) with two zero-risk residual harvests:
//  (1) x loadchunk moved from L1 warps (heavy group) to L2 warps (light group)
//  (2) L1 per-group x-loads hoisted ABOVE the FMA block (latency hidden)
// Everything else byte-identical to R11. 147 CTAs x 512 thr.

typedef unsigned long long u64;

#define TT     512
#define NBR    14
#define NBP    16
#define NTH    512
#define BTOT   2048
#define NCTA   147
#define PITCH  104

__device__ __forceinline__ u64 pack2(float lo, float hi) {
    u64 r; asm("mov.b64 %0, {%1, %2};" : "=l"(r) : "f"(lo), "f"(hi)); return r;
}
__device__ __forceinline__ float2 unpack2(u64 a) {
    float2 r; asm("mov.b64 {%0, %1}, %2;" : "=f"(r.x), "=f"(r.y) : "l"(a)); return r;
}
__device__ __forceinline__ void fma2(u64 &d, u64 a, u64 b) {
    asm("fma.rn.f32x2 %0, %1, %2, %0;" : "+l"(d) : "l"(a), "l"(b));
}
__device__ __forceinline__ float tanhap(float x) {
    float r; asm("tanh.approx.f32 %0, %1;" : "=f"(r) : "f"(x)); return r;
}
__device__ __forceinline__ float shx(float v, int m) {
    return __shfl_xor_sync(0xffffffffu, v, m);
}

__global__ __launch_bounds__(NTH, 1)
void lstm_fused(const float* __restrict__ x,
                const float* __restrict__ Wih1, const float* __restrict__ Whh1,
                const float* __restrict__ bih1, const float* __restrict__ bhh1,
                const float* __restrict__ Wih2, const float* __restrict__ Whh2,
                const float* __restrict__ bih2, const float* __restrict__ bhh2,
                const float* __restrict__ fc1w, const float* __restrict__ fc1b,
                const float* __restrict__ fc2w, const float* __restrict__ fc2b,
                float* __restrict__ out)
{
    __shared__ __align__(16) float  hcat[2][NBP][PITCH];
    __shared__ __align__(16) float4 xchunk[2][32][NBP];
    __shared__ float sfc1w[512], sfc1b[16], sfc2w[16], sfc2b[1];

    const int tid  = threadIdx.x;
    const int lane = tid & 31;
    const int wid  = tid >> 5;
    const int b0   = blockIdx.x * NBR;
    const bool bvalid = (tid < NBR) && (b0 + tid < BTOT);

    // ---- smem init ----
    for (int i = tid; i < 2 * NBP * PITCH; i += NTH) ((float*)hcat)[i] = 0.f;
    for (int i = tid; i < 512;             i += NTH) sfc1w[i] = fc1w[i];
    if (tid < 16) sfc1b[tid] = fc1b[tid];
    if (tid < 16) sfc2w[tid] = fc2w[tid];
    if (tid == 0) sfc2b[0] = fc2b[0];

    if (wid < 8) {
        // ================= Layer-1 warps (tid 0..255) =================
        const int wg    = wid;
        const int jslot = lane & 7;
        const int ks1   = lane >> 3;          // k-quarter (lane bits 3,4)
        const int j1    = wg * 8 + jslot;

        u64 w1[4][8];
        float wxs[4], b1r[4];
        #pragma unroll
        for (int g = 0; g < 4; ++g) {
            const float sc = (g == 2) ? 1.f : 0.5f;
            const int r1 = g * 64 + j1;
            #pragma unroll
            for (int m = 0; m < 8; ++m) {
                int k = 16 * ks1 + 2 * m;
                w1[g][m] = pack2(sc * Whh1[r1 * 64 + k], sc * Whh1[r1 * 64 + k + 1]);
            }
            wxs[g] = sc * Wih1[r1 * 4 + ks1];
            b1r[g] = sc * (bih1[r1] + bhh1[r1]);
        }
        int ro1[4], rox[4];
        #pragma unroll
        for (int q = 0; q < 4; ++q) {
            ro1[q] = (ks1 ^ q) * PITCH + 16 * ks1;
            rox[q] = (ks1 ^ q) * 4 + ks1;
        }
        const int so1 = ks1 * PITCH + j1;
        const int sb  = ks1 & 1;              // special group owner: batch 12+sb
        int ro1s[2], roxs[2];
        #pragma unroll
        for (int q = 0; q < 2; ++q) {
            ro1s[q] = (12 + (sb ^ q)) * PITCH + 16 * ks1;
            roxs[q] = (12 + (sb ^ q)) * 4 + ks1;
        }
        const int so1s = (12 + sb) * PITCH + j1;

        float c1[3] = {0.f, 0.f, 0.f};
        float c1s   = 0.f;
        __syncthreads();

        for (int s = 0; s <= TT; ++s) {
            if (s < TT) {
                const float* Ab = &hcat[(s + 1) & 1][0][0];   // h1(s-1)
                float*       Bb = &hcat[s & 1][0][0];         // h1(s) dest
                const float* Xb = (const float*)&xchunk[(s >> 5) & 1][s & 31][0];

                // ---- full groups: batches 0..11 ----
                #pragma unroll
                for (int G = 0; G < 3; ++G) {
                    // x loads FIRST: latency hidden under the FMA block below
                    float xv[4];
                    #pragma unroll
                    for (int q = 0; q < 4; ++q) xv[q] = Xb[16 * G + rox[q]];

                    u64 acc[4][4];
                    #pragma unroll
                    for (int g = 0; g < 4; ++g) {
                        acc[g][0] = pack2(b1r[g], 0.f);       // bias folded in
                        acc[g][1] = 0ULL; acc[g][2] = 0ULL; acc[g][3] = 0ULL;
                    }
                    #pragma unroll
                    for (int m = 0; m < 4; ++m)
                        #pragma unroll
                        for (int q = 0; q < 4; ++q) {
                            ulonglong2 hh =
                                *(const ulonglong2*)(Ab + 4 * G * PITCH + ro1[q] + 4 * m);
                            #pragma unroll
                            for (int g = 0; g < 4; ++g) {
                                fma2(acc[g][q], w1[g][2 * m],     hh.x);
                                fma2(acc[g][q], w1[g][2 * m + 1], hh.y);
                            }
                        }

                    float raw[4];
                    #pragma unroll
                    for (int g = 0; g < 4; ++g) {
                        float r0, r1, r2, r3;
                        { float2 f = unpack2(acc[g][0]); r0 = f.x + f.y; }
                        { float2 f = unpack2(acc[g][1]); r1 = f.x + f.y; }
                        { float2 f = unpack2(acc[g][2]); r2 = f.x + f.y; }
                        { float2 f = unpack2(acc[g][3]); r3 = f.x + f.y; }
                        r0 = fmaf(wxs[g], xv[0], r0);
                        r1 = fmaf(wxs[g], xv[1], r1);
                        r2 = fmaf(wxs[g], xv[2], r2);
                        r3 = fmaf(wxs[g], xv[3], r3);
                        float t1 = r0 + shx(r1, 8);
                        float t2 = r2 + shx(r3, 8);
                        raw[g] = t1 + shx(t2, 16);
                    }
                    float gi = fmaf(0.5f, tanhap(raw[0]), 0.5f);
                    float gf = fmaf(0.5f, tanhap(raw[1]), 0.5f);
                    float gg = tanhap(raw[2]);
                    float go = fmaf(0.5f, tanhap(raw[3]), 0.5f);
                    float c  = fmaf(gf, c1[G], gi * gg);
                    c1[G] = c;
                    Bb[4 * G * PITCH + so1] = go * tanhap(c);
                }

                // ---- special group: batches 12,13 (width-2 scatter) ----
                {
                    float xv0 = Xb[roxs[0]], xv1 = Xb[roxs[1]];   // hoisted

                    u64 acc[4][2];
                    #pragma unroll
                    for (int g = 0; g < 4; ++g) { acc[g][0] = 0ULL; acc[g][1] = 0ULL; }
                    #pragma unroll
                    for (int m = 0; m < 4; ++m)
                        #pragma unroll
                        for (int q = 0; q < 2; ++q) {
                            ulonglong2 hh = *(const ulonglong2*)(Ab + ro1s[q] + 4 * m);
                            #pragma unroll
                            for (int g = 0; g < 4; ++g) {
                                fma2(acc[g][q], w1[g][2 * m],     hh.x);
                                fma2(acc[g][q], w1[g][2 * m + 1], hh.y);
                            }
                        }
                    float raw[4];
                    #pragma unroll
                    for (int g = 0; g < 4; ++g) {
                        float r0, r1;
                        { float2 f = unpack2(acc[g][0]); r0 = f.x + f.y; }
                        { float2 f = unpack2(acc[g][1]); r1 = f.x + f.y; }
                        r0 = fmaf(wxs[g], xv0, r0);
                        r1 = fmaf(wxs[g], xv1, r1);
                        float z = r0 + shx(r1, 8);
                        raw[g] = z + shx(z, 16) + b1r[g];
                    }
                    float gi = fmaf(0.5f, tanhap(raw[0]), 0.5f);
                    float gf = fmaf(0.5f, tanhap(raw[1]), 0.5f);
                    float gg = tanhap(raw[2]);
                    float go = fmaf(0.5f, tanhap(raw[3]), 0.5f);
                    float c  = fmaf(gf, c1s, gi * gg);
                    c1s = c;
                    if (ks1 < 2)
                        Bb[so1s] = go * tanhap(c);
                }
            }
            __syncthreads();
        }
    } else {
        // ================= Layer-2 warps (tid 256..511) =================
        const int wg  = wid - 8;
        const int js2 = lane & 3;
        const int ks2 = (lane >> 2) & 7;      // k-eighth (lane bits 2,3,4)
        const int q2  = ks2 & 3;
        const int j2  = wg * 4 + js2;

        u64 w2[4][6];
        float b2r[4];
        #pragma unroll
        for (int g = 0; g < 4; ++g) {
            const float sc = (g == 2) ? 1.f : 0.5f;
            const int r2 = g * 32 + j2;
            #pragma unroll
            for (int m = 0; m < 6; ++m) {
                int k = 12 * ks2 + 2 * m;
                float lo = (k < 64)     ? Wih2[r2 * 64 + k]     : Whh2[r2 * 32 + k - 64];
                float hi = (k + 1 < 64) ? Wih2[r2 * 64 + k + 1] : Whh2[r2 * 32 + k - 63];
                w2[g][m] = pack2(sc * lo, sc * hi);
            }
            b2r[g] = sc * (bih2[r2] + bhh2[r2]);
        }
        int ro2[4];
        #pragma unroll
        for (int q = 0; q < 4; ++q)
            ro2[q] = (q2 ^ q) * PITCH + 12 * ks2;
        const int so2  = q2 * PITCH + 64 + j2;
        const int sb2  = q2 & 1;
        int ro2s[2];
        #pragma unroll
        for (int q = 0; q < 2; ++q)
            ro2s[q] = (12 + (sb2 ^ q)) * PITCH + 12 * ks2;
        const int so2s = (12 + sb2) * PITCH + 64 + j2;

        // x chunk loader now lives on the LIGHTER L2 group (tid 256..511)
        auto loadchunk = [&](int buf, int tbase) {
            #pragma unroll 2
            for (int idx = tid - 256; idx < 32 * NBR; idx += 256) {
                int b = idx >> 5, tq = idx & 31;
                float4 v = make_float4(0.f, 0.f, 0.f, 0.f);
                if (b0 + b < BTOT)
                    v = *(const float4*)(x + ((size_t)(b0 + b) * TT + tbase + tq) * 4);
                xchunk[buf][tq][b] = v;
            }
        };
        loadchunk(0, 0);

        float c2[3] = {0.f, 0.f, 0.f};
        float c2s   = 0.f;
        __syncthreads();

        // slot s computes h2(s-1): reads hcat[(s+1)&1] (h1(s-1)|h2(s-2)),
        // writes h2(s-1) -> hcat[s&1][64:96)
        for (int s = 0; s <= TT; ++s) {
            if (((s + 1) & 31) == 0 && (s + 1) < TT)
                loadchunk(((s + 1) >> 5) & 1, s + 1);

            if (s >= 1) {
                const float* Rb = &hcat[(s + 1) & 1][0][0];
                float*       Wb = &hcat[s & 1][0][0];

                // ---- full groups: batches 0..11 ----
                #pragma unroll
                for (int G = 0; G < 3; ++G) {
                    u64 acc[4][4];
                    #pragma unroll
                    for (int g = 0; g < 4; ++g) {
                        acc[g][0] = pack2(0.5f * b2r[g], 0.f);  // tree doubles it
                        acc[g][1] = 0ULL; acc[g][2] = 0ULL; acc[g][3] = 0ULL;
                    }
                    #pragma unroll
                    for (int m = 0; m < 3; ++m)
                        #pragma unroll
                        for (int q = 0; q < 4; ++q) {
                            ulonglong2 hh =
                                *(const ulonglong2*)(Rb + 4 * G * PITCH + ro2[q] + 4 * m);
                            #pragma unroll
                            for (int g = 0; g < 4; ++g) {
                                fma2(acc[g][q], w2[g][2 * m],     hh.x);
                                fma2(acc[g][q], w2[g][2 * m + 1], hh.y);
                            }
                        }
                    float raw[4];
                    #pragma unroll
                    for (int g = 0; g < 4; ++g) {
                        float r0, r1, r2, r3;
                        { float2 f = unpack2(acc[g][0]); r0 = f.x + f.y; }
                        { float2 f = unpack2(acc[g][1]); r1 = f.x + f.y; }
                        { float2 f = unpack2(acc[g][2]); r2 = f.x + f.y; }
                        { float2 f = unpack2(acc[g][3]); r3 = f.x + f.y; }
                        float t1 = r0 + shx(r1, 4);
                        float t2 = r2 + shx(r3, 4);
                        float tt = t1 + shx(t2, 8);
                        raw[g] = tt + shx(tt, 16);
                    }
                    float gi = fmaf(0.5f, tanhap(raw[0]), 0.5f);
                    float gf = fmaf(0.5f, tanhap(raw[1]), 0.5f);
                    float gg = tanhap(raw[2]);
                    float go = fmaf(0.5f, tanhap(raw[3]), 0.5f);
                    float c  = fmaf(gf, c2[G], gi * gg);
                    c2[G] = c;
                    if (lane < 16)
                        Wb[4 * G * PITCH + so2] = go * tanhap(c);
                }

                // ---- special group: batches 12,13 ----
                {
                    u64 acc[4][2];
                    #pragma unroll
                    for (int g = 0; g < 4; ++g) { acc[g][0] = 0ULL; acc[g][1] = 0ULL; }
                    #pragma unroll
                    for (int m = 0; m < 3; ++m)
                        #pragma unroll
                        for (int q = 0; q < 2; ++q) {
                            ulonglong2 hh = *(const ulonglong2*)(Rb + ro2s[q] + 4 * m);
                            #pragma unroll
                            for (int g = 0; g < 4; ++g) {
                                fma2(acc[g][q], w2[g][2 * m],     hh.x);
                                fma2(acc[g][q], w2[g][2 * m + 1], hh.y);
                            }
                        }
                    float raw[4];
                    #pragma unroll
                    for (int g = 0; g < 4; ++g) {
                        float r0, r1;
                        { float2 f = unpack2(acc[g][0]); r0 = f.x + f.y; }
                        { float2 f = unpack2(acc[g][1]); r1 = f.x + f.y; }
                        float z = r0 + shx(r1, 4);
                        z = z + shx(z, 8);
                        raw[g] = z + shx(z, 16) + b2r[g];
                    }
                    float gi = fmaf(0.5f, tanhap(raw[0]), 0.5f);
                    float gf = fmaf(0.5f, tanhap(raw[1]), 0.5f);
                    float gg = tanhap(raw[2]);
                    float go = fmaf(0.5f, tanhap(raw[3]), 0.5f);
                    float c  = fmaf(gf, c2s, gi * gg);
                    c2s = c;
                    if (ks2 < 2)
                        Wb[so2s] = go * tanhap(c);
                }
            }
            __syncthreads();
        }
    }

    __syncthreads();

    // ---- FC head: final h2(TT-1) in hcat[TT & 1][.][64:96) ----
    if (bvalid) {
        const float* hv = &hcat[TT & 1][tid][64];
        float o = sfc2b[0];
        #pragma unroll
        for (int f = 0; f < 16; ++f) {
            float acc = sfc1b[f];
            #pragma unroll
            for (int k = 0; k < 32; ++k)
                acc = fmaf(sfc1w[f * 32 + k], hv[k], acc);
            o = fmaf(sfc2w[f], fmaxf(acc, 0.f), o);
        }
        out[b0 + tid] = o;
    }
}

extern "C" void kernel_launch(void* const* d_in, const int* in_sizes, int n_in,
                              void* d_out, int out_size) {
    const float* x    = (const float*)d_in[0];
    const float* Wih1 = (const float*)d_in[1];
    const float* Whh1 = (const float*)d_in[2];
    const float* bih1 = (const float*)d_in[3];
    const float* bhh1 = (const float*)d_in[4];
    const float* Wih2 = (const float*)d_in[5];
    const float* Whh2 = (const float*)d_in[6];
    const float* bih2 = (const float*)d_in[7];
    const float* bhh2 = (const float*)d_in[8];
    const float* fc1w = (const float*)d_in[9];
    const float* fc1b = (const float*)d_in[10];
    const float* fc2w = (const float*)d_in[11];
    const float* fc2b = (const float*)d_in[12];
    float* out = (float*)d_out;

    lstm_fused<<<NCTA, NTH>>>(x, Wih1, Whh1, bih1, bhh1,
                              Wih2, Whh2, bih2, bhh2,
                              fc1w, fc1b, fc2w, fc2b, out);
}

// round 16
// speedup vs baseline: 1.0136x; 1.0136x over previous
#include <cuda_runtime.h>

// R16: one-directional pipeline decoupling of the R11 champion (1435.7us).
// h1 lives in a 4-deep ring; L1 runs up to 4 steps ahead of L2.
//   B_W[i] (ids 1-4): L1 arrives after writing h1(s) (i=s&3); L2 syncs before
//                     reading slot i. Doubles as L2's internal rendezvous.
//   B_R[i] (ids 5-8): L2 arrives after finishing slot i; L1 syncs before
//                     overwriting it. Doubles as L1's internal rendezvous.
//                     L2 pre-arrives all 4 (slots initially free).
// h2(u) -> ring[(u+1)&3][64:96) (L2-private columns, colocated with h1(u+1)).
// Compute bodies byte-identical to R11. 147 CTAs x 512 thr.

typedef unsigned long long u64;

#define TT     512
#define NBR    14
#define NBP    16
#define NTH    512
#define BTOT   2048
#define NCTA   147
#define PITCH  104

#define BW(i) (1 + (i))
#define BR(i) (5 + (i))

__device__ __forceinline__ void bar_sync(int id) {
    asm volatile("bar.sync %0, 512;" :: "r"(id) : "memory");
}
__device__ __forceinline__ void bar_arrive(int id) {
    asm volatile("bar.arrive %0, 512;" :: "r"(id) : "memory");
}
__device__ __forceinline__ u64 pack2(float lo, float hi) {
    u64 r; asm("mov.b64 %0, {%1, %2};" : "=l"(r) : "f"(lo), "f"(hi)); return r;
}
__device__ __forceinline__ float2 unpack2(u64 a) {
    float2 r; asm("mov.b64 {%0, %1}, %2;" : "=f"(r.x), "=f"(r.y) : "l"(a)); return r;
}
__device__ __forceinline__ void fma2(u64 &d, u64 a, u64 b) {
    asm("fma.rn.f32x2 %0, %1, %2, %0;" : "+l"(d) : "l"(a), "l"(b));
}
__device__ __forceinline__ float tanhap(float x) {
    float r; asm("tanh.approx.f32 %0, %1;" : "=f"(r) : "f"(x)); return r;
}
__device__ __forceinline__ float shx(float v, int m) {
    return __shfl_xor_sync(0xffffffffu, v, m);
}

__global__ __launch_bounds__(NTH, 1)
void lstm_fused(const float* __restrict__ x,
                const float* __restrict__ Wih1, const float* __restrict__ Whh1,
                const float* __restrict__ bih1, const float* __restrict__ bhh1,
                const float* __restrict__ Wih2, const float* __restrict__ Whh2,
                const float* __restrict__ bih2, const float* __restrict__ bhh2,
                const float* __restrict__ fc1w, const float* __restrict__ fc1b,
                const float* __restrict__ fc2w, const float* __restrict__ fc2b,
                float* __restrict__ out)
{
    __shared__ __align__(16) float  hcat[4][NBP][PITCH];     // h1|h2 ring
    __shared__ __align__(16) float4 xchunk[2][32][NBP];
    __shared__ float sfc1w[512], sfc1b[16], sfc2w[16], sfc2b[1];

    const int tid  = threadIdx.x;
    const int lane = tid & 31;
    const int wid  = tid >> 5;
    const int b0   = blockIdx.x * NBR;
    const bool bvalid = (tid < NBR) && (b0 + tid < BTOT);

    // ---- smem init ----
    for (int i = tid; i < 4 * NBP * PITCH; i += NTH) ((float*)hcat)[i] = 0.f;
    for (int i = tid; i < 512;             i += NTH) sfc1w[i] = fc1w[i];
    if (tid < 16) sfc1b[tid] = fc1b[tid];
    if (tid < 16) sfc2w[tid] = fc2w[tid];
    if (tid == 0) sfc2b[0] = fc2b[0];
    if (tid < 128) {
        int buf = tid >> 6, tq = (tid >> 1) & 31, b = 14 + (tid & 1);
        xchunk[buf][tq][b] = make_float4(0.f, 0.f, 0.f, 0.f);
    }

    if (wid < 8) {
        // ================= Layer-1 warps (tid 0..255) =================
        const int wg    = wid;
        const int jslot = lane & 7;
        const int ks1   = lane >> 3;          // k-quarter (lane bits 3,4)
        const int j1    = wg * 8 + jslot;

        u64 w1[4][8];
        float wxs[4], b1r[4];
        #pragma unroll
        for (int g = 0; g < 4; ++g) {
            const float sc = (g == 2) ? 1.f : 0.5f;
            const int r1 = g * 64 + j1;
            #pragma unroll
            for (int m = 0; m < 8; ++m) {
                int k = 16 * ks1 + 2 * m;
                w1[g][m] = pack2(sc * Whh1[r1 * 64 + k], sc * Whh1[r1 * 64 + k + 1]);
            }
            wxs[g] = sc * Wih1[r1 * 4 + ks1];
            b1r[g] = sc * (bih1[r1] + bhh1[r1]);
        }
        int ro1[4], rox[4];
        #pragma unroll
        for (int q = 0; q < 4; ++q) {
            ro1[q] = (ks1 ^ q) * PITCH + 16 * ks1;
            rox[q] = (ks1 ^ q) * 4 + ks1;
        }
        const int so1 = ks1 * PITCH + j1;
        const int sb  = ks1 & 1;              // special group owner: batch 12+sb
        int ro1s[2], roxs[2];
        #pragma unroll
        for (int q = 0; q < 2; ++q) {
            ro1s[q] = (12 + (sb ^ q)) * PITCH + 16 * ks1;
            roxs[q] = (12 + (sb ^ q)) * 4 + ks1;
        }
        const int so1s = (12 + sb) * PITCH + j1;

        auto loadchunk = [&](int buf, int tbase) {
            #pragma unroll 2
            for (int idx = tid; idx < 32 * NBR; idx += 256) {
                int b = idx >> 5, tq = idx & 31;
                float4 v = make_float4(0.f, 0.f, 0.f, 0.f);
                if (b0 + b < BTOT)
                    v = *(const float4*)(x + ((size_t)(b0 + b) * TT + tbase + tq) * 4);
                xchunk[buf][tq][b] = v;
            }
        };
        loadchunk(0, 0);

        float c1[3] = {0.f, 0.f, 0.f};
        float c1s   = 0.f;
        __syncthreads();

        for (int s = 0; s < TT; ++s) {
            // slot (s&3) free (L2 done with it or initial credit) +
            // L1-internal rendezvous (orders our own STS(s-1) -> LDS(s))
            bar_sync(BR(s & 3));

            if (((s + 1) & 31) == 0 && (s + 1) < TT)
                loadchunk(((s + 1) >> 5) & 1, s + 1);

            const float* Ab = &hcat[(s + 3) & 3][0][0];   // h1(s-1)
            float*       Bb = &hcat[s & 3][0][0];         // h1(s) dest
            const float* Xb = (const float*)&xchunk[(s >> 5) & 1][s & 31][0];

            // ---- full groups: batches 0..11 ----
            #pragma unroll
            for (int G = 0; G < 3; ++G) {
                u64 acc[4][4];
                #pragma unroll
                for (int g = 0; g < 4; ++g) {
                    acc[g][0] = pack2(b1r[g], 0.f);       // bias folded in
                    acc[g][1] = 0ULL; acc[g][2] = 0ULL; acc[g][3] = 0ULL;
                }
                #pragma unroll
                for (int m = 0; m < 4; ++m)
                    #pragma unroll
                    for (int q = 0; q < 4; ++q) {
                        ulonglong2 hh =
                            *(const ulonglong2*)(Ab + 4 * G * PITCH + ro1[q] + 4 * m);
                        #pragma unroll
                        for (int g = 0; g < 4; ++g) {
                            fma2(acc[g][q], w1[g][2 * m],     hh.x);
                            fma2(acc[g][q], w1[g][2 * m + 1], hh.y);
                        }
                    }
                float xv[4];
                #pragma unroll
                for (int q = 0; q < 4; ++q) xv[q] = Xb[16 * G + rox[q]];

                float raw[4];
                #pragma unroll
                for (int g = 0; g < 4; ++g) {
                    float r0, r1, r2, r3;
                    { float2 f = unpack2(acc[g][0]); r0 = f.x + f.y; }
                    { float2 f = unpack2(acc[g][1]); r1 = f.x + f.y; }
                    { float2 f = unpack2(acc[g][2]); r2 = f.x + f.y; }
                    { float2 f = unpack2(acc[g][3]); r3 = f.x + f.y; }
                    r0 = fmaf(wxs[g], xv[0], r0);
                    r1 = fmaf(wxs[g], xv[1], r1);
                    r2 = fmaf(wxs[g], xv[2], r2);
                    r3 = fmaf(wxs[g], xv[3], r3);
                    float t1 = r0 + shx(r1, 8);
                    float t2 = r2 + shx(r3, 8);
                    raw[g] = t1 + shx(t2, 16);
                }
                float gi = fmaf(0.5f, tanhap(raw[0]), 0.5f);
                float gf = fmaf(0.5f, tanhap(raw[1]), 0.5f);
                float gg = tanhap(raw[2]);
                float go = fmaf(0.5f, tanhap(raw[3]), 0.5f);
                float c  = fmaf(gf, c1[G], gi * gg);
                c1[G] = c;
                Bb[4 * G * PITCH + so1] = go * tanhap(c);
            }

            // ---- special group: batches 12,13 (width-2 scatter) ----
            {
                u64 acc[4][2];
                #pragma unroll
                for (int g = 0; g < 4; ++g) { acc[g][0] = 0ULL; acc[g][1] = 0ULL; }
                #pragma unroll
                for (int m = 0; m < 4; ++m)
                    #pragma unroll
                    for (int q = 0; q < 2; ++q) {
                        ulonglong2 hh = *(const ulonglong2*)(Ab + ro1s[q] + 4 * m);
                        #pragma unroll
                        for (int g = 0; g < 4; ++g) {
                            fma2(acc[g][q], w1[g][2 * m],     hh.x);
                            fma2(acc[g][q], w1[g][2 * m + 1], hh.y);
                        }
                    }
                float xv0 = Xb[roxs[0]], xv1 = Xb[roxs[1]];
                float raw[4];
                #pragma unroll
                for (int g = 0; g < 4; ++g) {
                    float r0, r1;
                    { float2 f = unpack2(acc[g][0]); r0 = f.x + f.y; }
                    { float2 f = unpack2(acc[g][1]); r1 = f.x + f.y; }
                    r0 = fmaf(wxs[g], xv0, r0);
                    r1 = fmaf(wxs[g], xv1, r1);
                    float z = r0 + shx(r1, 8);
                    raw[g] = z + shx(z, 16) + b1r[g];
                }
                float gi = fmaf(0.5f, tanhap(raw[0]), 0.5f);
                float gf = fmaf(0.5f, tanhap(raw[1]), 0.5f);
                float gg = tanhap(raw[2]);
                float go = fmaf(0.5f, tanhap(raw[3]), 0.5f);
                float c  = fmaf(gf, c1s, gi * gg);
                c1s = c;
                if (ks1 < 2)
                    Bb[so1s] = go * tanhap(c);
            }

            bar_arrive(BW(s & 3));   // h1(s) published
        }
    } else {
        // ================= Layer-2 warps (tid 256..511) =================
        const int wg  = wid - 8;
        const int js2 = lane & 3;
        const int ks2 = (lane >> 2) & 7;      // k-eighth (lane bits 2,3,4)
        const int q2  = ks2 & 3;
        const int j2  = wg * 4 + js2;

        u64 w2[4][6];
        float b2r[4];
        #pragma unroll
        for (int g = 0; g < 4; ++g) {
            const float sc = (g == 2) ? 1.f : 0.5f;
            const int r2 = g * 32 + j2;
            #pragma unroll
            for (int m = 0; m < 6; ++m) {
                int k = 12 * ks2 + 2 * m;
                float lo = (k < 64)     ? Wih2[r2 * 64 + k]     : Whh2[r2 * 32 + k - 64];
                float hi = (k + 1 < 64) ? Wih2[r2 * 64 + k + 1] : Whh2[r2 * 32 + k - 63];
                w2[g][m] = pack2(sc * lo, sc * hi);
            }
            b2r[g] = sc * (bih2[r2] + bhh2[r2]);
        }
        int ro2[4];
        #pragma unroll
        for (int q = 0; q < 4; ++q)
            ro2[q] = (q2 ^ q) * PITCH + 12 * ks2;
        const int so2  = q2 * PITCH + 64 + j2;
        const int sb2  = q2 & 1;
        int ro2s[2];
        #pragma unroll
        for (int q = 0; q < 2; ++q)
            ro2s[q] = (12 + (sb2 ^ q)) * PITCH + 12 * ks2;
        const int so2s = (12 + sb2) * PITCH + 64 + j2;

        float c2[3] = {0.f, 0.f, 0.f};
        float c2s   = 0.f;
        __syncthreads();

        // slots initially free: pre-arrive all 4 B_R barriers
        bar_arrive(BR(0)); bar_arrive(BR(1));
        bar_arrive(BR(2)); bar_arrive(BR(3));

        // step u computes h2(u): reads ring[u&3] = h1(u)|h2(u-1),
        // writes h2(u) -> ring[(u+1)&3][64:96)
        for (int u = 0; u < TT; ++u) {
            bar_sync(BW(u & 3));              // h1(u) ready + L2 rendezvous
            const float* Rb = &hcat[u & 3][0][0];
            float*       Wb = &hcat[(u + 1) & 3][0][0];

            // ---- full groups: batches 0..11 ----
            #pragma unroll
            for (int G = 0; G < 3; ++G) {
                u64 acc[4][4];
                #pragma unroll
                for (int g = 0; g < 4; ++g) {
                    acc[g][0] = pack2(0.5f * b2r[g], 0.f);  // tree doubles it
                    acc[g][1] = 0ULL; acc[g][2] = 0ULL; acc[g][3] = 0ULL;
                }
                #pragma unroll
                for (int m = 0; m < 3; ++m)
                    #pragma unroll
                    for (int q = 0; q < 4; ++q) {
                        ulonglong2 hh =
                            *(const ulonglong2*)(Rb + 4 * G * PITCH + ro2[q] + 4 * m);
                        #pragma unroll
                        for (int g = 0; g < 4; ++g) {
                            fma2(acc[g][q], w2[g][2 * m],     hh.x);
                            fma2(acc[g][q], w2[g][2 * m + 1], hh.y);
                        }
                    }
                float raw[4];
                #pragma unroll
                for (int g = 0; g < 4; ++g) {
                    float r0, r1, r2, r3;
                    { float2 f = unpack2(acc[g][0]); r0 = f.x + f.y; }
                    { float2 f = unpack2(acc[g][1]); r1 = f.x + f.y; }
                    { float2 f = unpack2(acc[g][2]); r2 = f.x + f.y; }
                    { float2 f = unpack2(acc[g][3]); r3 = f.x + f.y; }
                    float t1 = r0 + shx(r1, 4);
                    float t2 = r2 + shx(r3, 4);
                    float tt = t1 + shx(t2, 8);
                    raw[g] = tt + shx(tt, 16);
                }
                float gi = fmaf(0.5f, tanhap(raw[0]), 0.5f);
                float gf = fmaf(0.5f, tanhap(raw[1]), 0.5f);
                float gg = tanhap(raw[2]);
                float go = fmaf(0.5f, tanhap(raw[3]), 0.5f);
                float c  = fmaf(gf, c2[G], gi * gg);
                c2[G] = c;
                if (lane < 16)
                    Wb[4 * G * PITCH + so2] = go * tanhap(c);
            }

            // ---- special group: batches 12,13 ----
            {
                u64 acc[4][2];
                #pragma unroll
                for (int g = 0; g < 4; ++g) { acc[g][0] = 0ULL; acc[g][1] = 0ULL; }
                #pragma unroll
                for (int m = 0; m < 3; ++m)
                    #pragma unroll
                    for (int q = 0; q < 2; ++q) {
                        ulonglong2 hh = *(const ulonglong2*)(Rb + ro2s[q] + 4 * m);
                        #pragma unroll
                        for (int g = 0; g < 4; ++g) {
                            fma2(acc[g][q], w2[g][2 * m],     hh.x);
                            fma2(acc[g][q], w2[g][2 * m + 1], hh.y);
                        }
                    }
                float raw[4];
                #pragma unroll
                for (int g = 0; g < 4; ++g) {
                    float r0, r1;
                    { float2 f = unpack2(acc[g][0]); r0 = f.x + f.y; }
                    { float2 f = unpack2(acc[g][1]); r1 = f.x + f.y; }
                    float z = r0 + shx(r1, 4);
                    z = z + shx(z, 8);
                    raw[g] = z + shx(z, 16) + b2r[g];
                }
                float gi = fmaf(0.5f, tanhap(raw[0]), 0.5f);
                float gf = fmaf(0.5f, tanhap(raw[1]), 0.5f);
                float gg = tanhap(raw[2]);
                float go = fmaf(0.5f, tanhap(raw[3]), 0.5f);
                float c  = fmaf(gf, c2s, gi * gg);
                c2s = c;
                if (ks2 < 2)
                    Wb[so2s] = go * tanhap(c);
            }

            bar_arrive(BR(u & 3));            // slot (u&3) free for L1(u+4)
        }
    }

    __syncthreads();

    // ---- FC head: final h2(511) in ring[(512)&3] = ring[0][.][64:96) ----
    if (bvalid) {
        const float* hv = &hcat[0][tid][64];
        float o = sfc2b[0];
        #pragma unroll
        for (int f = 0; f < 16; ++f) {
            float acc = sfc1b[f];
            #pragma unroll
            for (int k = 0; k < 32; ++k)
                acc = fmaf(sfc1w[f * 32 + k], hv[k], acc);
            o = fmaf(sfc2w[f], fmaxf(acc, 0.f), o);
        }
        out[b0 + tid] = o;
    }
}

extern "C" void kernel_launch(void* const* d_in, const int* in_sizes, int n_in,
                              void* d_out, int out_size) {
    const float* x    = (const float*)d_in[0];
    const float* Wih1 = (const float*)d_in[1];
    const float* Whh1 = (const float*)d_in[2];
    const float* bih1 = (const float*)d_in[3];
    const float* bhh1 = (const float*)d_in[4];
    const float* Wih2 = (const float*)d_in[5];
    const float* Whh2 = (const float*)d_in[6];
    const float* bih2 = (const float*)d_in[7];
    const float* bhh2 = (const float*)d_in[8];
    const float* fc1w = (const float*)d_in[9];
    const float* fc1b = (const float*)d_in[10];
    const float* fc2w = (const float*)d_in[11];
    const float* fc2b = (const float*)d_in[12];
    float* out = (float*)d_out;

    lstm_fused<<<NCTA, NTH>>>(x, Wih1, Whh1, bih1, bhh1,
                              Wih2, Whh2, bih2, bhh2,
                              fc1w, fc1b, fc2w, fc2b, out);
}